// round 9
// baseline (speedup 1.0000x reference)
#include <cuda_runtime.h>
#include <cstdint>

#define N_NODES 100000
#define N_EDGES 1600000
#define F 128
#define NCLS 64

// ---------------- scratch (no allocation allowed; __device__ globals) ------
__device__ float g_bufA[(size_t)N_NODES * F];
__device__ float g_bufB[(size_t)N_NODES * F];
__device__ int   g_counts[N_NODES];
__device__ int   g_rowstart[N_NODES + 1];
__device__ int   g_cursor[N_NODES];
__device__ int   g_eidx[N_EDGES];
__device__ int   g_blocksums[128];

// ---------------- CSR build -----------------------------------------------
__global__ void k_hist(const int* __restrict__ dst) {
    int e = blockIdx.x * blockDim.x + threadIdx.x;
    if (e < N_EDGES) atomicAdd(&g_counts[dst[e]], 1);
}

__global__ void k_scan1() {
    __shared__ int s[1024];
    int t = threadIdx.x;
    int i = blockIdx.x * 1024 + t;
    int v = (i < N_NODES) ? g_counts[i] : 0;
    s[t] = v;
    __syncthreads();
    for (int off = 1; off < 1024; off <<= 1) {
        int x = (t >= off) ? s[t - off] : 0;
        __syncthreads();
        s[t] += x;
        __syncthreads();
    }
    if (i < N_NODES) g_rowstart[i] = s[t] - v;   // exclusive
    if (t == 1023) g_blocksums[blockIdx.x] = s[1023];
}

__global__ void k_scan2(int nblocks) {
    __shared__ int s[128];
    int t = threadIdx.x;
    int v = (t < nblocks) ? g_blocksums[t] : 0;
    s[t] = v;
    __syncthreads();
    for (int off = 1; off < 128; off <<= 1) {
        int x = (t >= off) ? s[t - off] : 0;
        __syncthreads();
        s[t] += x;
        __syncthreads();
    }
    if (t < nblocks) g_blocksums[t] = s[t] - v;  // exclusive
}

__global__ void k_scan3() {
    int i = blockIdx.x * blockDim.x + threadIdx.x;
    if (i < N_NODES) {
        int r = g_rowstart[i] + g_blocksums[i >> 10];
        g_rowstart[i] = r;
        g_cursor[i]   = r;
    }
    if (i == N_NODES) g_rowstart[N_NODES] = N_EDGES;
}

__global__ void k_scatter(const int* __restrict__ src, const int* __restrict__ dst) {
    int e = blockIdx.x * blockDim.x + threadIdx.x;
    if (e < N_EDGES) {
        int p = atomicAdd(&g_cursor[dst[e]], 1);
        g_eidx[p] = src[e];
    }
}

// ---------------- tf32 helpers --------------------------------------------
__device__ __forceinline__ uint32_t f2tf32(float f) {
    uint32_t u;
    asm("cvt.rna.tf32.f32 %0, %1;" : "=r"(u) : "f"(f));
    return u;
}

__device__ __forceinline__ void mma_tf32(float c[4],
                                         uint32_t a0, uint32_t a1, uint32_t a2, uint32_t a3,
                                         uint32_t b0, uint32_t b1) {
    asm volatile(
        "mma.sync.aligned.m16n8k8.row.col.f32.tf32.tf32.f32 "
        "{%0,%1,%2,%3}, {%4,%5,%6,%7}, {%8,%9}, {%0,%1,%2,%3};\n"
        : "+f"(c[0]), "+f"(c[1]), "+f"(c[2]), "+f"(c[3])
        : "r"(a0), "r"(a1), "r"(a2), "r"(a3), "r"(b0), "r"(b1));
}

// ---------------- plain GEMM (layer 0 only): C = A @ W --------------------
template<int NOUT>
__global__ void __launch_bounds__(512, 1)
k_gemm_tc(const float* __restrict__ A, const float* __restrict__ W,
          float* __restrict__ C) {
    constexpr int BM  = 256;
    constexpr int AST = 132;
    constexpr int WST = 136;
    constexpr int NTILES = NOUT / 32;

    extern __shared__ uint32_t sm[];
    uint32_t* As = sm;
    uint32_t* Ws = sm + BM * AST;

    int tid = threadIdx.x;
    int m0 = blockIdx.x * BM;

    for (int idx = tid * 4; idx < 128 * NOUT; idx += 512 * 4) {
        int k = idx / NOUT, n = idx % NOUT;
        float4 v = *(const float4*)&W[idx];
        uint32_t* p = &Ws[k * WST + n];
        p[0] = f2tf32(v.x); p[1] = f2tf32(v.y);
        p[2] = f2tf32(v.z); p[3] = f2tf32(v.w);
    }
    for (int idx = tid; idx < BM * 32; idx += 512) {
        int m = idx >> 5, kq = idx & 31;
        float4 v = make_float4(0.f, 0.f, 0.f, 0.f);
        if (m0 + m < N_NODES)
            v = *(const float4*)&A[(size_t)(m0 + m) * 128 + kq * 4];
        uint32_t* p = &As[m * AST + kq * 4];
        p[0] = f2tf32(v.x); p[1] = f2tf32(v.y);
        p[2] = f2tf32(v.z); p[3] = f2tf32(v.w);
    }
    __syncthreads();

    int wid  = tid >> 5, lane = tid & 31;
    int wm = wid & 3, wn = wid >> 2;
    int mbase = wm * 64;
    int nbase = wn * (NOUT / 4);
    int r = lane >> 2, c = lane & 3;

    float acc[4][NTILES][4];
#pragma unroll
    for (int mt = 0; mt < 4; ++mt)
#pragma unroll
        for (int nt = 0; nt < NTILES; ++nt)
#pragma unroll
            for (int i = 0; i < 4; ++i) acc[mt][nt][i] = 0.f;

#pragma unroll 2
    for (int k0 = 0; k0 < 128; k0 += 8) {
        uint32_t af[4][4];
#pragma unroll
        for (int mt = 0; mt < 4; ++mt) {
            int row = mbase + mt * 16 + r;
            af[mt][0] = As[row * AST + k0 + c];
            af[mt][1] = As[(row + 8) * AST + k0 + c];
            af[mt][2] = As[row * AST + k0 + c + 4];
            af[mt][3] = As[(row + 8) * AST + k0 + c + 4];
        }
        uint32_t bf[NTILES][2];
#pragma unroll
        for (int nt = 0; nt < NTILES; ++nt) {
            int col = nbase + nt * 8 + r;
            bf[nt][0] = Ws[(k0 + c) * WST + col];
            bf[nt][1] = Ws[(k0 + c + 4) * WST + col];
        }
#pragma unroll
        for (int mt = 0; mt < 4; ++mt)
#pragma unroll
            for (int nt = 0; nt < NTILES; ++nt)
                mma_tf32(acc[mt][nt], af[mt][0], af[mt][1], af[mt][2], af[mt][3],
                         bf[nt][0], bf[nt][1]);
    }

#pragma unroll
    for (int nt = 0; nt < NTILES; ++nt) {
        int col = nbase + nt * 8 + 2 * c;
#pragma unroll
        for (int mt = 0; mt < 4; ++mt) {
            int row = m0 + mbase + mt * 16 + r;
            if (row < N_NODES)
                *(float2*)&C[(size_t)row * NOUT + col] =
                    make_float2(acc[mt][nt][0], acc[mt][nt][1]);
            if (row + 8 < N_NODES)
                *(float2*)&C[(size_t)(row + 8) * NOUT + col] =
                    make_float2(acc[mt][nt][2], acc[mt][nt][3]);
        }
    }
}

// ---------------- FUSED: agg(Y)+norm+bias+relu -> tf32 A-tile -> GEMM -----
// h[m] = relu(norm[m] * segsum(Y[src]) + bias)  built straight into smem,
// then C = h @ W. Y is 128-wide; C is NOUT-wide.
template<int NOUT>
__global__ void __launch_bounds__(512, 1)
k_fused_agg_gemm(const float* __restrict__ Y, const float* __restrict__ norm,
                 const float* __restrict__ bias, const float* __restrict__ W,
                 float* __restrict__ C) {
    constexpr int BM  = 256;
    constexpr int AST = 132;
    constexpr int WST = 136;
    constexpr int NTILES = NOUT / 32;

    extern __shared__ uint32_t sm[];
    uint32_t* As = sm;
    uint32_t* Ws = sm + BM * AST;

    int tid = threadIdx.x;
    int wid = tid >> 5, lane = tid & 31;
    int m0 = blockIdx.x * BM;

    // load W -> Ws (tf32)
    for (int idx = tid * 4; idx < 128 * NOUT; idx += 512 * 4) {
        int k = idx / NOUT, n = idx % NOUT;
        float4 v = *(const float4*)&W[idx];
        uint32_t* p = &Ws[k * WST + n];
        p[0] = f2tf32(v.x); p[1] = f2tf32(v.y);
        p[2] = f2tf32(v.z); p[3] = f2tf32(v.w);
    }

    // aggregate 16 nodes per warp straight into As (tf32)
    float4 b4 = *(const float4*)(bias + lane * 4);
#pragma unroll 1
    for (int i = 0; i < 16; ++i) {
        int m = wid * 16 + i;
        int node = m0 + m;
        float ax = 0.f, ay = 0.f, az = 0.f, aw = 0.f;
        if (node < N_NODES) {
            int beg = g_rowstart[node];
            int end = g_rowstart[node + 1];
            int e = beg;
            for (; e + 4 <= end; e += 4) {
                int s0 = g_eidx[e + 0];
                int s1 = g_eidx[e + 1];
                int s2 = g_eidx[e + 2];
                int s3 = g_eidx[e + 3];
                float4 v0 = *(const float4*)(Y + (size_t)s0 * F + lane * 4);
                float4 v1 = *(const float4*)(Y + (size_t)s1 * F + lane * 4);
                float4 v2 = *(const float4*)(Y + (size_t)s2 * F + lane * 4);
                float4 v3 = *(const float4*)(Y + (size_t)s3 * F + lane * 4);
                ax += v0.x + v1.x + v2.x + v3.x;
                ay += v0.y + v1.y + v2.y + v3.y;
                az += v0.z + v1.z + v2.z + v3.z;
                aw += v0.w + v1.w + v2.w + v3.w;
            }
            for (; e < end; ++e) {
                int s = g_eidx[e];
                float4 v = *(const float4*)(Y + (size_t)s * F + lane * 4);
                ax += v.x; ay += v.y; az += v.z; aw += v.w;
            }
            float nf = norm[node];
            ax = fmaxf(ax * nf + b4.x, 0.f);
            ay = fmaxf(ay * nf + b4.y, 0.f);
            az = fmaxf(az * nf + b4.z, 0.f);
            aw = fmaxf(aw * nf + b4.w, 0.f);
        }
        uint32_t* p = &As[m * AST + lane * 4];
        p[0] = f2tf32(ax); p[1] = f2tf32(ay);
        p[2] = f2tf32(az); p[3] = f2tf32(aw);
    }
    __syncthreads();

    // MMA phase
    int wm = wid & 3, wn = wid >> 2;
    int mbase = wm * 64;
    int nbase = wn * (NOUT / 4);
    int r = lane >> 2, c = lane & 3;

    float acc[4][NTILES][4];
#pragma unroll
    for (int mt = 0; mt < 4; ++mt)
#pragma unroll
        for (int nt = 0; nt < NTILES; ++nt)
#pragma unroll
            for (int i = 0; i < 4; ++i) acc[mt][nt][i] = 0.f;

#pragma unroll 2
    for (int k0 = 0; k0 < 128; k0 += 8) {
        uint32_t af[4][4];
#pragma unroll
        for (int mt = 0; mt < 4; ++mt) {
            int row = mbase + mt * 16 + r;
            af[mt][0] = As[row * AST + k0 + c];
            af[mt][1] = As[(row + 8) * AST + k0 + c];
            af[mt][2] = As[row * AST + k0 + c + 4];
            af[mt][3] = As[(row + 8) * AST + k0 + c + 4];
        }
        uint32_t bf[NTILES][2];
#pragma unroll
        for (int nt = 0; nt < NTILES; ++nt) {
            int col = nbase + nt * 8 + r;
            bf[nt][0] = Ws[(k0 + c) * WST + col];
            bf[nt][1] = Ws[(k0 + c + 4) * WST + col];
        }
#pragma unroll
        for (int mt = 0; mt < 4; ++mt)
#pragma unroll
            for (int nt = 0; nt < NTILES; ++nt)
                mma_tf32(acc[mt][nt], af[mt][0], af[mt][1], af[mt][2], af[mt][3],
                         bf[nt][0], bf[nt][1]);
    }

#pragma unroll
    for (int nt = 0; nt < NTILES; ++nt) {
        int col = nbase + nt * 8 + 2 * c;
#pragma unroll
        for (int mt = 0; mt < 4; ++mt) {
            int row = m0 + mbase + mt * 16 + r;
            if (row < N_NODES)
                *(float2*)&C[(size_t)row * NOUT + col] =
                    make_float2(acc[mt][nt][0], acc[mt][nt][1]);
            if (row + 8 < N_NODES)
                *(float2*)&C[(size_t)(row + 8) * NOUT + col] =
                    make_float2(acc[mt][nt][2], acc[mt][nt][3]);
        }
    }
}

// ---------------- final aggregation (64-wide) + norm + bias ---------------
__global__ void k_agg64_bias(const float* __restrict__ Y, const float* __restrict__ norm,
                             const float* __restrict__ bias, float* __restrict__ out) {
    int w = (blockIdx.x * blockDim.x + threadIdx.x) >> 5;
    int lane = threadIdx.x & 31;
    if (w >= N_NODES) return;
    int beg = g_rowstart[w];
    int end = g_rowstart[w + 1];

    float ax = 0.f, ay = 0.f;
    int e = beg;
    for (; e + 4 <= end; e += 4) {
        int s0 = g_eidx[e + 0];
        int s1 = g_eidx[e + 1];
        int s2 = g_eidx[e + 2];
        int s3 = g_eidx[e + 3];
        float2 v0 = *(const float2*)(Y + (size_t)s0 * NCLS + lane * 2);
        float2 v1 = *(const float2*)(Y + (size_t)s1 * NCLS + lane * 2);
        float2 v2 = *(const float2*)(Y + (size_t)s2 * NCLS + lane * 2);
        float2 v3 = *(const float2*)(Y + (size_t)s3 * NCLS + lane * 2);
        ax += v0.x + v1.x + v2.x + v3.x;
        ay += v0.y + v1.y + v2.y + v3.y;
    }
    for (; e < end; ++e) {
        int s = g_eidx[e];
        float2 v = *(const float2*)(Y + (size_t)s * NCLS + lane * 2);
        ax += v.x; ay += v.y;
    }
    float nf = norm[w];
    float2 b = *(const float2*)(bias + lane * 2);
    float2 r = make_float2(ax * nf + b.x, ay * nf + b.y);
    *(float2*)(out + (size_t)w * NCLS + lane * 2) = r;
}

// ---------------- launch ---------------------------------------------------
extern "C" void kernel_launch(void* const* d_in, const int* in_sizes, int n_in,
                              void* d_out, int out_size) {
    const float* features = (const float*)d_in[0];
    const float* norm     = (const float*)d_in[1];
    const float* W0       = (const float*)d_in[2];
    const float* b0       = (const float*)d_in[3];
    const float* W1       = (const float*)d_in[4];
    const float* b1       = (const float*)d_in[5];
    const float* W2       = (const float*)d_in[6];
    const float* b2       = (const float*)d_in[7];
    const int*   src      = (const int*)d_in[8];
    const int*   dst      = (const int*)d_in[9];
    float* out = (float*)d_out;

    float *bufA = nullptr, *bufB = nullptr;
    int* countsPtr = nullptr;
    cudaGetSymbolAddress((void**)&bufA, g_bufA);
    cudaGetSymbolAddress((void**)&bufB, g_bufB);
    cudaGetSymbolAddress((void**)&countsPtr, g_counts);

    const int SM_GEMM = (256 * 132 + 128 * 136) * 4;   // 204800 B
    cudaFuncSetAttribute(k_gemm_tc<128>, cudaFuncAttributeMaxDynamicSharedMemorySize, SM_GEMM);
    cudaFuncSetAttribute(k_fused_agg_gemm<128>, cudaFuncAttributeMaxDynamicSharedMemorySize, SM_GEMM);
    cudaFuncSetAttribute(k_fused_agg_gemm<64>,  cudaFuncAttributeMaxDynamicSharedMemorySize, SM_GEMM);

    static cudaStream_t s2 = nullptr;
    static cudaEvent_t evFork = nullptr, evJoin = nullptr;
    if (!s2) {
        cudaStreamCreateWithFlags(&s2, cudaStreamNonBlocking);
        cudaEventCreateWithFlags(&evFork, cudaEventDisableTiming);
        cudaEventCreateWithFlags(&evJoin, cudaEventDisableTiming);
    }

    dim3 aggGrid((N_NODES + 7) / 8);
    int gemmGrid = (N_NODES + 255) / 256;       // 391

    // ---- fork: gemm0 (Y0 = feat @ W0, independent of CSR) on s2 ----
    cudaEventRecord(evFork, 0);
    cudaStreamWaitEvent(s2, evFork, 0);
    k_gemm_tc<128><<<gemmGrid, 512, SM_GEMM, s2>>>(features, W0, bufA);
    cudaEventRecord(evJoin, s2);

    // ---- CSR build (by dst), concurrent with gemm0 ----
    cudaMemsetAsync(countsPtr, 0, N_NODES * sizeof(int));
    k_hist<<<(N_EDGES + 255) / 256, 256>>>(dst);
    int nb = (N_NODES + 1023) / 1024;   // 98
    k_scan1<<<nb, 1024>>>();
    k_scan2<<<1, 128>>>(nb);
    k_scan3<<<(N_NODES + 1 + 255) / 256, 256>>>();
    k_scatter<<<(N_EDGES + 255) / 256, 256>>>(src, dst);

    cudaStreamWaitEvent(0, evJoin, 0);

    // fused layer boundaries:
    // Y1 = relu(norm*segsum(Y0[src])+b0) @ W1
    k_fused_agg_gemm<128><<<gemmGrid, 512, SM_GEMM>>>(bufA, norm, b0, W1, bufB);
    // Y2 = relu(norm*segsum(Y1[src])+b1) @ W2   (64-wide)
    k_fused_agg_gemm<64><<<gemmGrid, 512, SM_GEMM>>>(bufB, norm, b1, W2, bufA);
    // out = norm * segsum(Y2[src]) + b2
    k_agg64_bias<<<aggGrid, 256>>>(bufA, norm, b2, out);
}

// round 10
// speedup vs baseline: 1.4575x; 1.4575x over previous
#include <cuda_runtime.h>
#include <cuda_fp16.h>
#include <cstdint>

#define N_NODES 100000
#define N_EDGES 1600000
#define F 128
#define NCLS 64

// ---------------- scratch (no allocation allowed; __device__ globals) ------
__device__ __half g_buf16[(size_t)N_NODES * F];   // Y0 / Y1 (fp16, reused)
__device__ float  g_bufA[(size_t)N_NODES * F];    // Y2 (fp32, 64-wide used)
__device__ float  g_bufB[(size_t)N_NODES * F];    // h1 / h2 (fp32, reused)
__device__ int    g_counts[N_NODES];
__device__ int    g_rowstart[N_NODES + 1];
__device__ int    g_cursor[N_NODES];
__device__ int    g_eidx[N_EDGES];
__device__ int    g_blocksums[128];

// ---------------- CSR build -----------------------------------------------
__global__ void k_hist(const int* __restrict__ dst) {
    int e = blockIdx.x * blockDim.x + threadIdx.x;
    if (e < N_EDGES) atomicAdd(&g_counts[dst[e]], 1);
}

__global__ void k_scan1() {
    __shared__ int s[1024];
    int t = threadIdx.x;
    int i = blockIdx.x * 1024 + t;
    int v = (i < N_NODES) ? g_counts[i] : 0;
    s[t] = v;
    __syncthreads();
    for (int off = 1; off < 1024; off <<= 1) {
        int x = (t >= off) ? s[t - off] : 0;
        __syncthreads();
        s[t] += x;
        __syncthreads();
    }
    if (i < N_NODES) g_rowstart[i] = s[t] - v;   // exclusive
    if (t == 1023) g_blocksums[blockIdx.x] = s[1023];
}

__global__ void k_scan2(int nblocks) {
    __shared__ int s[128];
    int t = threadIdx.x;
    int v = (t < nblocks) ? g_blocksums[t] : 0;
    s[t] = v;
    __syncthreads();
    for (int off = 1; off < 128; off <<= 1) {
        int x = (t >= off) ? s[t - off] : 0;
        __syncthreads();
        s[t] += x;
        __syncthreads();
    }
    if (t < nblocks) g_blocksums[t] = s[t] - v;  // exclusive
}

__global__ void k_scan3() {
    int i = blockIdx.x * blockDim.x + threadIdx.x;
    if (i < N_NODES) {
        int r = g_rowstart[i] + g_blocksums[i >> 10];
        g_rowstart[i] = r;
        g_cursor[i]   = r;
    }
    if (i == N_NODES) g_rowstart[N_NODES] = N_EDGES;
}

__global__ void k_scatter(const int* __restrict__ src, const int* __restrict__ dst) {
    int e = blockIdx.x * blockDim.x + threadIdx.x;
    if (e < N_EDGES) {
        int p = atomicAdd(&g_cursor[dst[e]], 1);
        g_eidx[p] = src[e];
    }
}

// ---------------- aggregation (fp16 Y, 128-wide) + norm + bias + relu -----
// h[node] = relu(norm[node] * segsum(Y16[src]) + bias), h fp32.
// Warp per node; lane handles 4 halves (8 B) per row.
__global__ void k_agg16_epi(const __half* __restrict__ Y16, const float* __restrict__ norm,
                            const float* __restrict__ bias, float* __restrict__ out) {
    int w = (blockIdx.x * blockDim.x + threadIdx.x) >> 5;
    int lane = threadIdx.x & 31;
    if (w >= N_NODES) return;
    int beg = g_rowstart[w];
    int end = g_rowstart[w + 1];

    float ax = 0.f, ay = 0.f, az = 0.f, aw = 0.f;
    int e = beg;
    for (; e + 4 <= end; e += 4) {
        int s0 = g_eidx[e + 0];
        int s1 = g_eidx[e + 1];
        int s2 = g_eidx[e + 2];
        int s3 = g_eidx[e + 3];
        float2 r0 = *(const float2*)(Y16 + (size_t)s0 * F + lane * 4);
        float2 r1 = *(const float2*)(Y16 + (size_t)s1 * F + lane * 4);
        float2 r2 = *(const float2*)(Y16 + (size_t)s2 * F + lane * 4);
        float2 r3 = *(const float2*)(Y16 + (size_t)s3 * F + lane * 4);
        float2 a0 = __half22float2(*(__half2*)&r0.x), b0 = __half22float2(*(__half2*)&r0.y);
        float2 a1 = __half22float2(*(__half2*)&r1.x), b1 = __half22float2(*(__half2*)&r1.y);
        float2 a2 = __half22float2(*(__half2*)&r2.x), b2 = __half22float2(*(__half2*)&r2.y);
        float2 a3 = __half22float2(*(__half2*)&r3.x), b3 = __half22float2(*(__half2*)&r3.y);
        ax += a0.x + a1.x + a2.x + a3.x;
        ay += a0.y + a1.y + a2.y + a3.y;
        az += b0.x + b1.x + b2.x + b3.x;
        aw += b0.y + b1.y + b2.y + b3.y;
    }
    for (; e < end; ++e) {
        int s = g_eidx[e];
        float2 r = *(const float2*)(Y16 + (size_t)s * F + lane * 4);
        float2 a = __half22float2(*(__half2*)&r.x), b = __half22float2(*(__half2*)&r.y);
        ax += a.x; ay += a.y; az += b.x; aw += b.y;
    }
    float nf = norm[w];
    float4 b4 = *(const float4*)(bias + lane * 4);
    float4 r = make_float4(fmaxf(ax * nf + b4.x, 0.f),
                           fmaxf(ay * nf + b4.y, 0.f),
                           fmaxf(az * nf + b4.z, 0.f),
                           fmaxf(aw * nf + b4.w, 0.f));
    *(float4*)(out + (size_t)w * F + lane * 4) = r;
}

// ---------------- final aggregation (fp32 Y, 64-wide) + norm + bias -------
__global__ void k_agg64_bias(const float* __restrict__ Y, const float* __restrict__ norm,
                             const float* __restrict__ bias, float* __restrict__ out) {
    int w = (blockIdx.x * blockDim.x + threadIdx.x) >> 5;
    int lane = threadIdx.x & 31;
    if (w >= N_NODES) return;
    int beg = g_rowstart[w];
    int end = g_rowstart[w + 1];

    float ax = 0.f, ay = 0.f;
    int e = beg;
    for (; e + 4 <= end; e += 4) {
        int s0 = g_eidx[e + 0];
        int s1 = g_eidx[e + 1];
        int s2 = g_eidx[e + 2];
        int s3 = g_eidx[e + 3];
        float2 v0 = *(const float2*)(Y + (size_t)s0 * NCLS + lane * 2);
        float2 v1 = *(const float2*)(Y + (size_t)s1 * NCLS + lane * 2);
        float2 v2 = *(const float2*)(Y + (size_t)s2 * NCLS + lane * 2);
        float2 v3 = *(const float2*)(Y + (size_t)s3 * NCLS + lane * 2);
        ax += v0.x + v1.x + v2.x + v3.x;
        ay += v0.y + v1.y + v2.y + v3.y;
    }
    for (; e < end; ++e) {
        int s = g_eidx[e];
        float2 v = *(const float2*)(Y + (size_t)s * NCLS + lane * 2);
        ax += v.x; ay += v.y;
    }
    float nf = norm[w];
    float2 b = *(const float2*)(bias + lane * 2);
    float2 r = make_float2(ax * nf + b.x, ay * nf + b.y);
    *(float2*)(out + (size_t)w * NCLS + lane * 2) = r;
}

// ---------------- tf32 helpers --------------------------------------------
__device__ __forceinline__ uint32_t f2tf32(float f) {
    uint32_t u;
    asm("cvt.rna.tf32.f32 %0, %1;" : "=r"(u) : "f"(f));
    return u;
}

__device__ __forceinline__ void mma_tf32(float c[4],
                                         uint32_t a0, uint32_t a1, uint32_t a2, uint32_t a3,
                                         uint32_t b0, uint32_t b1) {
    asm volatile(
        "mma.sync.aligned.m16n8k8.row.col.f32.tf32.tf32.f32 "
        "{%0,%1,%2,%3}, {%4,%5,%6,%7}, {%8,%9}, {%0,%1,%2,%3};\n"
        : "+f"(c[0]), "+f"(c[1]), "+f"(c[2]), "+f"(c[3])
        : "r"(a0), "r"(a1), "r"(a2), "r"(a3), "r"(b0), "r"(b1));
}

// ---------------- GEMM: C = A @ W, output fp16 or fp32 --------------------
// BLOCK_M = 256 rows, 512 threads (16 warps), warp grid 4(m) x 4(n).
template<int NOUT, bool HALF_OUT>
__global__ void __launch_bounds__(512, 1)
k_gemm_tc(const float* __restrict__ A, const float* __restrict__ W,
          void* __restrict__ Cv) {
    constexpr int BM  = 256;
    constexpr int AST = 132;            // conflict-free A stride (words)
    constexpr int WST = 136;            // conflict-free W stride (words)
    constexpr int NTILES = NOUT / 32;

    extern __shared__ uint32_t sm[];
    uint32_t* As = sm;
    uint32_t* Ws = sm + BM * AST;

    int tid = threadIdx.x;
    int m0 = blockIdx.x * BM;

    for (int idx = tid * 4; idx < 128 * NOUT; idx += 512 * 4) {
        int k = idx / NOUT, n = idx % NOUT;
        float4 v = *(const float4*)&W[idx];
        uint32_t* p = &Ws[k * WST + n];
        p[0] = f2tf32(v.x); p[1] = f2tf32(v.y);
        p[2] = f2tf32(v.z); p[3] = f2tf32(v.w);
    }
    for (int idx = tid; idx < BM * 32; idx += 512) {
        int m = idx >> 5, kq = idx & 31;
        float4 v = make_float4(0.f, 0.f, 0.f, 0.f);
        if (m0 + m < N_NODES)
            v = *(const float4*)&A[(size_t)(m0 + m) * 128 + kq * 4];
        uint32_t* p = &As[m * AST + kq * 4];
        p[0] = f2tf32(v.x); p[1] = f2tf32(v.y);
        p[2] = f2tf32(v.z); p[3] = f2tf32(v.w);
    }
    __syncthreads();

    int wid  = tid >> 5, lane = tid & 31;
    int wm = wid & 3, wn = wid >> 2;
    int mbase = wm * 64;
    int nbase = wn * (NOUT / 4);
    int r = lane >> 2, c = lane & 3;

    float acc[4][NTILES][4];
#pragma unroll
    for (int mt = 0; mt < 4; ++mt)
#pragma unroll
        for (int nt = 0; nt < NTILES; ++nt)
#pragma unroll
            for (int i = 0; i < 4; ++i) acc[mt][nt][i] = 0.f;

#pragma unroll 2
    for (int k0 = 0; k0 < 128; k0 += 8) {
        uint32_t af[4][4];
#pragma unroll
        for (int mt = 0; mt < 4; ++mt) {
            int row = mbase + mt * 16 + r;
            af[mt][0] = As[row * AST + k0 + c];
            af[mt][1] = As[(row + 8) * AST + k0 + c];
            af[mt][2] = As[row * AST + k0 + c + 4];
            af[mt][3] = As[(row + 8) * AST + k0 + c + 4];
        }
        uint32_t bf[NTILES][2];
#pragma unroll
        for (int nt = 0; nt < NTILES; ++nt) {
            int col = nbase + nt * 8 + r;
            bf[nt][0] = Ws[(k0 + c) * WST + col];
            bf[nt][1] = Ws[(k0 + c + 4) * WST + col];
        }
#pragma unroll
        for (int mt = 0; mt < 4; ++mt)
#pragma unroll
            for (int nt = 0; nt < NTILES; ++nt)
                mma_tf32(acc[mt][nt], af[mt][0], af[mt][1], af[mt][2], af[mt][3],
                         bf[nt][0], bf[nt][1]);
    }

#pragma unroll
    for (int nt = 0; nt < NTILES; ++nt) {
        int col = nbase + nt * 8 + 2 * c;
#pragma unroll
        for (int mt = 0; mt < 4; ++mt) {
            int row = m0 + mbase + mt * 16 + r;
            if (HALF_OUT) {
                __half* C16 = (__half*)Cv;
                if (row < N_NODES)
                    *(__half2*)&C16[(size_t)row * NOUT + col] =
                        __floats2half2_rn(acc[mt][nt][0], acc[mt][nt][1]);
                if (row + 8 < N_NODES)
                    *(__half2*)&C16[(size_t)(row + 8) * NOUT + col] =
                        __floats2half2_rn(acc[mt][nt][2], acc[mt][nt][3]);
            } else {
                float* C = (float*)Cv;
                if (row < N_NODES)
                    *(float2*)&C[(size_t)row * NOUT + col] =
                        make_float2(acc[mt][nt][0], acc[mt][nt][1]);
                if (row + 8 < N_NODES)
                    *(float2*)&C[(size_t)(row + 8) * NOUT + col] =
                        make_float2(acc[mt][nt][2], acc[mt][nt][3]);
            }
        }
    }
}

// ---------------- launch ---------------------------------------------------
extern "C" void kernel_launch(void* const* d_in, const int* in_sizes, int n_in,
                              void* d_out, int out_size) {
    const float* features = (const float*)d_in[0];
    const float* norm     = (const float*)d_in[1];
    const float* W0       = (const float*)d_in[2];
    const float* b0       = (const float*)d_in[3];
    const float* W1       = (const float*)d_in[4];
    const float* b1       = (const float*)d_in[5];
    const float* W2       = (const float*)d_in[6];
    const float* b2       = (const float*)d_in[7];
    const int*   src      = (const int*)d_in[8];
    const int*   dst      = (const int*)d_in[9];
    float* out = (float*)d_out;

    __half* buf16 = nullptr;
    float *bufA = nullptr, *bufB = nullptr;
    int* countsPtr = nullptr;
    cudaGetSymbolAddress((void**)&buf16, g_buf16);
    cudaGetSymbolAddress((void**)&bufA, g_bufA);
    cudaGetSymbolAddress((void**)&bufB, g_bufB);
    cudaGetSymbolAddress((void**)&countsPtr, g_counts);

    const int SM_GEMM = (256 * 132 + 128 * 136) * 4;   // 204800 B
    cudaFuncSetAttribute(k_gemm_tc<128, true >, cudaFuncAttributeMaxDynamicSharedMemorySize, SM_GEMM);
    cudaFuncSetAttribute(k_gemm_tc<64,  false>, cudaFuncAttributeMaxDynamicSharedMemorySize, SM_GEMM);

    static cudaStream_t s2 = nullptr;
    static cudaEvent_t evFork = nullptr, evJoin = nullptr;
    if (!s2) {
        cudaStreamCreateWithFlags(&s2, cudaStreamNonBlocking);
        cudaEventCreateWithFlags(&evFork, cudaEventDisableTiming);
        cudaEventCreateWithFlags(&evJoin, cudaEventDisableTiming);
    }

    dim3 aggGrid((N_NODES + 7) / 8);            // warp per node
    int gemmGrid = (N_NODES + 255) / 256;       // 391

    // ---- fork: gemm0 (Y0 = feat @ W0 -> fp16, independent of CSR) on s2 ----
    cudaEventRecord(evFork, 0);
    cudaStreamWaitEvent(s2, evFork, 0);
    k_gemm_tc<128, true><<<gemmGrid, 512, SM_GEMM, s2>>>(features, W0, buf16);
    cudaEventRecord(evJoin, s2);

    // ---- CSR build (by dst), concurrent with gemm0 ----
    cudaMemsetAsync(countsPtr, 0, N_NODES * sizeof(int));
    k_hist<<<(N_EDGES + 255) / 256, 256>>>(dst);
    int nb = (N_NODES + 1023) / 1024;   // 98
    k_scan1<<<nb, 1024>>>();
    k_scan2<<<1, 128>>>(nb);
    k_scan3<<<(N_NODES + 1 + 255) / 256, 256>>>();
    k_scatter<<<(N_EDGES + 255) / 256, 256>>>(src, dst);

    cudaStreamWaitEvent(0, evJoin, 0);

    // layer 0 epilogue: h1 = relu(norm * segsum(Y0[src]) + b0)   (fp16 gather)
    k_agg16_epi<<<aggGrid, 256>>>(buf16, norm, b0, bufB);
    // layer 1: Y1 = h1 @ W1 -> fp16 (reuse buf16); h2 = relu(norm*segsum(Y1)+b1)
    k_gemm_tc<128, true><<<gemmGrid, 512, SM_GEMM>>>(bufB, W1, buf16);
    k_agg16_epi<<<aggGrid, 256>>>(buf16, norm, b1, bufB);
    // layer 2: Y2 = h2 @ W2 (fp32, 64-wide); out = norm * segsum(Y2[src]) + b2
    k_gemm_tc<64, false><<<gemmGrid, 512, SM_GEMM>>>(bufB, W2, bufA);
    k_agg64_bias<<<aggGrid, 256>>>(bufA, norm, b2, out);
}

// round 11
// speedup vs baseline: 1.6598x; 1.1388x over previous
#include <cuda_runtime.h>
#include <cuda_fp16.h>
#include <cstdint>

#define N_NODES 100000
#define N_EDGES 1600000
#define F 128
#define NCLS 64

// ---------------- scratch (no allocation allowed; __device__ globals) ------
__device__ __half g_bufY[(size_t)N_NODES * F];    // Y0 / Y1 / Y2 (fp16)
__device__ __half g_bufH[(size_t)N_NODES * F];    // h1 / h2 (fp16)
__device__ int    g_counts[N_NODES];
__device__ int    g_rowstart[N_NODES + 1];
__device__ int    g_cursor[N_NODES];
__device__ int    g_eidx[N_EDGES];
__device__ int    g_blocksums[128];

// ---------------- CSR build -----------------------------------------------
__global__ void k_hist(const int* __restrict__ dst) {
    int e = blockIdx.x * blockDim.x + threadIdx.x;
    if (e < N_EDGES) atomicAdd(&g_counts[dst[e]], 1);
}

__global__ void k_scan1() {
    __shared__ int s[1024];
    int t = threadIdx.x;
    int i = blockIdx.x * 1024 + t;
    int v = (i < N_NODES) ? g_counts[i] : 0;
    s[t] = v;
    __syncthreads();
    for (int off = 1; off < 1024; off <<= 1) {
        int x = (t >= off) ? s[t - off] : 0;
        __syncthreads();
        s[t] += x;
        __syncthreads();
    }
    if (i < N_NODES) g_rowstart[i] = s[t] - v;   // exclusive
    if (t == 1023) g_blocksums[blockIdx.x] = s[1023];
}

__global__ void k_scan2(int nblocks) {
    __shared__ int s[128];
    int t = threadIdx.x;
    int v = (t < nblocks) ? g_blocksums[t] : 0;
    s[t] = v;
    __syncthreads();
    for (int off = 1; off < 128; off <<= 1) {
        int x = (t >= off) ? s[t - off] : 0;
        __syncthreads();
        s[t] += x;
        __syncthreads();
    }
    if (t < nblocks) g_blocksums[t] = s[t] - v;  // exclusive
}

__global__ void k_scan3() {
    int i = blockIdx.x * blockDim.x + threadIdx.x;
    if (i < N_NODES) {
        int r = g_rowstart[i] + g_blocksums[i >> 10];
        g_rowstart[i] = r;
        g_cursor[i]   = r;
    }
    if (i == N_NODES) g_rowstart[N_NODES] = N_EDGES;
}

__global__ void k_scatter(const int* __restrict__ src, const int* __restrict__ dst) {
    int e = blockIdx.x * blockDim.x + threadIdx.x;
    if (e < N_EDGES) {
        int p = atomicAdd(&g_cursor[dst[e]], 1);
        g_eidx[p] = src[e];
    }
}

// ---------------- helpers --------------------------------------------------
__device__ __forceinline__ void acc_half4(float& ax, float& ay, float& az, float& aw,
                                          float2 r) {
    float2 a = __half22float2(*(__half2*)&r.x);
    float2 b = __half22float2(*(__half2*)&r.y);
    ax += a.x; ay += a.y; az += b.x; aw += b.y;
}

// ---------------- agg (fp16 Y, 128-wide) -> h fp16 (norm+bias+relu) -------
__global__ void k_agg16_epi(const __half* __restrict__ Y16, const float* __restrict__ norm,
                            const float* __restrict__ bias, __half* __restrict__ out) {
    int w = (blockIdx.x * blockDim.x + threadIdx.x) >> 5;
    int lane = threadIdx.x & 31;
    if (w >= N_NODES) return;
    int beg = g_rowstart[w];
    int end = g_rowstart[w + 1];

    float ax = 0.f, ay = 0.f, az = 0.f, aw = 0.f;
    int e = beg;
    // 8-wide: 8 outstanding row-loads per lane
    for (; e + 8 <= end; e += 8) {
        int s0 = g_eidx[e + 0], s1 = g_eidx[e + 1];
        int s2 = g_eidx[e + 2], s3 = g_eidx[e + 3];
        int s4 = g_eidx[e + 4], s5 = g_eidx[e + 5];
        int s6 = g_eidx[e + 6], s7 = g_eidx[e + 7];
        float2 r0 = *(const float2*)(Y16 + (size_t)s0 * F + lane * 4);
        float2 r1 = *(const float2*)(Y16 + (size_t)s1 * F + lane * 4);
        float2 r2 = *(const float2*)(Y16 + (size_t)s2 * F + lane * 4);
        float2 r3 = *(const float2*)(Y16 + (size_t)s3 * F + lane * 4);
        float2 r4 = *(const float2*)(Y16 + (size_t)s4 * F + lane * 4);
        float2 r5 = *(const float2*)(Y16 + (size_t)s5 * F + lane * 4);
        float2 r6 = *(const float2*)(Y16 + (size_t)s6 * F + lane * 4);
        float2 r7 = *(const float2*)(Y16 + (size_t)s7 * F + lane * 4);
        acc_half4(ax, ay, az, aw, r0); acc_half4(ax, ay, az, aw, r1);
        acc_half4(ax, ay, az, aw, r2); acc_half4(ax, ay, az, aw, r3);
        acc_half4(ax, ay, az, aw, r4); acc_half4(ax, ay, az, aw, r5);
        acc_half4(ax, ay, az, aw, r6); acc_half4(ax, ay, az, aw, r7);
    }
    for (; e + 4 <= end; e += 4) {
        int s0 = g_eidx[e + 0], s1 = g_eidx[e + 1];
        int s2 = g_eidx[e + 2], s3 = g_eidx[e + 3];
        float2 r0 = *(const float2*)(Y16 + (size_t)s0 * F + lane * 4);
        float2 r1 = *(const float2*)(Y16 + (size_t)s1 * F + lane * 4);
        float2 r2 = *(const float2*)(Y16 + (size_t)s2 * F + lane * 4);
        float2 r3 = *(const float2*)(Y16 + (size_t)s3 * F + lane * 4);
        acc_half4(ax, ay, az, aw, r0); acc_half4(ax, ay, az, aw, r1);
        acc_half4(ax, ay, az, aw, r2); acc_half4(ax, ay, az, aw, r3);
    }
    for (; e < end; ++e) {
        int s = g_eidx[e];
        float2 r = *(const float2*)(Y16 + (size_t)s * F + lane * 4);
        acc_half4(ax, ay, az, aw, r);
    }
    float nf = norm[w];
    float4 b4 = *(const float4*)(bias + lane * 4);
    float hx = fmaxf(ax * nf + b4.x, 0.f);
    float hy = fmaxf(ay * nf + b4.y, 0.f);
    float hz = fmaxf(az * nf + b4.z, 0.f);
    float hw = fmaxf(aw * nf + b4.w, 0.f);
    __half2 p0 = __floats2half2_rn(hx, hy);
    __half2 p1 = __floats2half2_rn(hz, hw);
    float2 packed;
    *(__half2*)&packed.x = p0;
    *(__half2*)&packed.y = p1;
    *(float2*)(out + (size_t)w * F + lane * 4) = packed;
}

// ---------------- final agg (fp16 Y2, 64-wide) + norm + bias -> fp32 out --
__global__ void k_agg64_bias(const __half* __restrict__ Y16, const float* __restrict__ norm,
                             const float* __restrict__ bias, float* __restrict__ out) {
    int w = (blockIdx.x * blockDim.x + threadIdx.x) >> 5;
    int lane = threadIdx.x & 31;
    if (w >= N_NODES) return;
    int beg = g_rowstart[w];
    int end = g_rowstart[w + 1];

    float ax = 0.f, ay = 0.f;
    int e = beg;
    for (; e + 8 <= end; e += 8) {
        int s0 = g_eidx[e + 0], s1 = g_eidx[e + 1];
        int s2 = g_eidx[e + 2], s3 = g_eidx[e + 3];
        int s4 = g_eidx[e + 4], s5 = g_eidx[e + 5];
        int s6 = g_eidx[e + 6], s7 = g_eidx[e + 7];
        __half2 v0 = *(const __half2*)(Y16 + (size_t)s0 * NCLS + lane * 2);
        __half2 v1 = *(const __half2*)(Y16 + (size_t)s1 * NCLS + lane * 2);
        __half2 v2 = *(const __half2*)(Y16 + (size_t)s2 * NCLS + lane * 2);
        __half2 v3 = *(const __half2*)(Y16 + (size_t)s3 * NCLS + lane * 2);
        __half2 v4 = *(const __half2*)(Y16 + (size_t)s4 * NCLS + lane * 2);
        __half2 v5 = *(const __half2*)(Y16 + (size_t)s5 * NCLS + lane * 2);
        __half2 v6 = *(const __half2*)(Y16 + (size_t)s6 * NCLS + lane * 2);
        __half2 v7 = *(const __half2*)(Y16 + (size_t)s7 * NCLS + lane * 2);
        float2 f0 = __half22float2(v0), f1 = __half22float2(v1);
        float2 f2 = __half22float2(v2), f3 = __half22float2(v3);
        float2 f4 = __half22float2(v4), f5 = __half22float2(v5);
        float2 f6 = __half22float2(v6), f7 = __half22float2(v7);
        ax += f0.x + f1.x + f2.x + f3.x + f4.x + f5.x + f6.x + f7.x;
        ay += f0.y + f1.y + f2.y + f3.y + f4.y + f5.y + f6.y + f7.y;
    }
    for (; e + 4 <= end; e += 4) {
        int s0 = g_eidx[e + 0], s1 = g_eidx[e + 1];
        int s2 = g_eidx[e + 2], s3 = g_eidx[e + 3];
        __half2 v0 = *(const __half2*)(Y16 + (size_t)s0 * NCLS + lane * 2);
        __half2 v1 = *(const __half2*)(Y16 + (size_t)s1 * NCLS + lane * 2);
        __half2 v2 = *(const __half2*)(Y16 + (size_t)s2 * NCLS + lane * 2);
        __half2 v3 = *(const __half2*)(Y16 + (size_t)s3 * NCLS + lane * 2);
        float2 f0 = __half22float2(v0), f1 = __half22float2(v1);
        float2 f2 = __half22float2(v2), f3 = __half22float2(v3);
        ax += f0.x + f1.x + f2.x + f3.x;
        ay += f0.y + f1.y + f2.y + f3.y;
    }
    for (; e < end; ++e) {
        int s = g_eidx[e];
        float2 f = __half22float2(*(const __half2*)(Y16 + (size_t)s * NCLS + lane * 2));
        ax += f.x; ay += f.y;
    }
    float nf = norm[w];
    float2 b = *(const float2*)(bias + lane * 2);
    *(float2*)(out + (size_t)w * NCLS + lane * 2) = make_float2(ax * nf + b.x, ay * nf + b.y);
}

// ---------------- tf32 helpers --------------------------------------------
__device__ __forceinline__ uint32_t f2tf32(float f) {
    uint32_t u;
    asm("cvt.rna.tf32.f32 %0, %1;" : "=r"(u) : "f"(f));
    return u;
}

__device__ __forceinline__ void mma_tf32(float c[4],
                                         uint32_t a0, uint32_t a1, uint32_t a2, uint32_t a3,
                                         uint32_t b0, uint32_t b1) {
    asm volatile(
        "mma.sync.aligned.m16n8k8.row.col.f32.tf32.tf32.f32 "
        "{%0,%1,%2,%3}, {%4,%5,%6,%7}, {%8,%9}, {%0,%1,%2,%3};\n"
        : "+f"(c[0]), "+f"(c[1]), "+f"(c[2]), "+f"(c[3])
        : "r"(a0), "r"(a1), "r"(a2), "r"(a3), "r"(b0), "r"(b1));
}

// ---------------- GEMM: C(fp16) = A @ W; A fp32 or fp16 -------------------
// BLOCK_M = 256 rows, 512 threads (16 warps), warp grid 4(m) x 4(n).
template<int NOUT, bool HALF_IN>
__global__ void __launch_bounds__(512, 1)
k_gemm_tc(const void* __restrict__ Av, const float* __restrict__ W,
          __half* __restrict__ C16) {
    constexpr int BM  = 256;
    constexpr int AST = 132;            // conflict-free A stride (words)
    constexpr int WST = 136;            // conflict-free W stride (words)
    constexpr int NTILES = NOUT / 32;

    extern __shared__ uint32_t sm[];
    uint32_t* As = sm;
    uint32_t* Ws = sm + BM * AST;

    int tid = threadIdx.x;
    int m0 = blockIdx.x * BM;

    // W -> Ws (tf32)
    for (int idx = tid * 4; idx < 128 * NOUT; idx += 512 * 4) {
        int k = idx / NOUT, n = idx % NOUT;
        float4 v = *(const float4*)&W[idx];
        uint32_t* p = &Ws[k * WST + n];
        p[0] = f2tf32(v.x); p[1] = f2tf32(v.y);
        p[2] = f2tf32(v.z); p[3] = f2tf32(v.w);
    }

    // A tile -> As (tf32), fp32 or fp16 source
    if (HALF_IN) {
        const __half* A16 = (const __half*)Av;
        for (int idx = tid; idx < BM * 16; idx += 512) {
            int m = idx >> 4, kq = idx & 15;          // kq = 8-half chunk
            float4 v = make_float4(0.f, 0.f, 0.f, 0.f);
            if (m0 + m < N_NODES)
                v = *(const float4*)(A16 + (size_t)(m0 + m) * 128 + kq * 8);
            const __half2* h2 = (const __half2*)&v;
            uint32_t* p = &As[m * AST + kq * 8];
#pragma unroll
            for (int j = 0; j < 4; ++j) {
                float2 f = __half22float2(h2[j]);
                p[2 * j]     = f2tf32(f.x);
                p[2 * j + 1] = f2tf32(f.y);
            }
        }
    } else {
        const float* A = (const float*)Av;
        for (int idx = tid; idx < BM * 32; idx += 512) {
            int m = idx >> 5, kq = idx & 31;
            float4 v = make_float4(0.f, 0.f, 0.f, 0.f);
            if (m0 + m < N_NODES)
                v = *(const float4*)&A[(size_t)(m0 + m) * 128 + kq * 4];
            uint32_t* p = &As[m * AST + kq * 4];
            p[0] = f2tf32(v.x); p[1] = f2tf32(v.y);
            p[2] = f2tf32(v.z); p[3] = f2tf32(v.w);
        }
    }
    __syncthreads();

    int wid  = tid >> 5, lane = tid & 31;
    int wm = wid & 3, wn = wid >> 2;
    int mbase = wm * 64;
    int nbase = wn * (NOUT / 4);
    int r = lane >> 2, c = lane & 3;

    float acc[4][NTILES][4];
#pragma unroll
    for (int mt = 0; mt < 4; ++mt)
#pragma unroll
        for (int nt = 0; nt < NTILES; ++nt)
#pragma unroll
            for (int i = 0; i < 4; ++i) acc[mt][nt][i] = 0.f;

#pragma unroll 2
    for (int k0 = 0; k0 < 128; k0 += 8) {
        uint32_t af[4][4];
#pragma unroll
        for (int mt = 0; mt < 4; ++mt) {
            int row = mbase + mt * 16 + r;
            af[mt][0] = As[row * AST + k0 + c];
            af[mt][1] = As[(row + 8) * AST + k0 + c];
            af[mt][2] = As[row * AST + k0 + c + 4];
            af[mt][3] = As[(row + 8) * AST + k0 + c + 4];
        }
        uint32_t bf[NTILES][2];
#pragma unroll
        for (int nt = 0; nt < NTILES; ++nt) {
            int col = nbase + nt * 8 + r;
            bf[nt][0] = Ws[(k0 + c) * WST + col];
            bf[nt][1] = Ws[(k0 + c + 4) * WST + col];
        }
#pragma unroll
        for (int mt = 0; mt < 4; ++mt)
#pragma unroll
            for (int nt = 0; nt < NTILES; ++nt)
                mma_tf32(acc[mt][nt], af[mt][0], af[mt][1], af[mt][2], af[mt][3],
                         bf[nt][0], bf[nt][1]);
    }

#pragma unroll
    for (int nt = 0; nt < NTILES; ++nt) {
        int col = nbase + nt * 8 + 2 * c;
#pragma unroll
        for (int mt = 0; mt < 4; ++mt) {
            int row = m0 + mbase + mt * 16 + r;
            if (row < N_NODES)
                *(__half2*)&C16[(size_t)row * NOUT + col] =
                    __floats2half2_rn(acc[mt][nt][0], acc[mt][nt][1]);
            if (row + 8 < N_NODES)
                *(__half2*)&C16[(size_t)(row + 8) * NOUT + col] =
                    __floats2half2_rn(acc[mt][nt][2], acc[mt][nt][3]);
        }
    }
}

// ---------------- launch ---------------------------------------------------
extern "C" void kernel_launch(void* const* d_in, const int* in_sizes, int n_in,
                              void* d_out, int out_size) {
    const float* features = (const float*)d_in[0];
    const float* norm     = (const float*)d_in[1];
    const float* W0       = (const float*)d_in[2];
    const float* b0       = (const float*)d_in[3];
    const float* W1       = (const float*)d_in[4];
    const float* b1       = (const float*)d_in[5];
    const float* W2       = (const float*)d_in[6];
    const float* b2       = (const float*)d_in[7];
    const int*   src      = (const int*)d_in[8];
    const int*   dst      = (const int*)d_in[9];
    float* out = (float*)d_out;

    __half *bufY = nullptr, *bufH = nullptr;
    int* countsPtr = nullptr;
    cudaGetSymbolAddress((void**)&bufY, g_bufY);
    cudaGetSymbolAddress((void**)&bufH, g_bufH);
    cudaGetSymbolAddress((void**)&countsPtr, g_counts);

    const int SM_GEMM = (256 * 132 + 128 * 136) * 4;   // 204800 B
    cudaFuncSetAttribute(k_gemm_tc<128, false>, cudaFuncAttributeMaxDynamicSharedMemorySize, SM_GEMM);
    cudaFuncSetAttribute(k_gemm_tc<128, true >, cudaFuncAttributeMaxDynamicSharedMemorySize, SM_GEMM);
    cudaFuncSetAttribute(k_gemm_tc<64,  true >, cudaFuncAttributeMaxDynamicSharedMemorySize, SM_GEMM);

    static cudaStream_t s2 = nullptr;
    static cudaEvent_t evFork = nullptr, evJoin = nullptr;
    if (!s2) {
        cudaStreamCreateWithFlags(&s2, cudaStreamNonBlocking);
        cudaEventCreateWithFlags(&evFork, cudaEventDisableTiming);
        cudaEventCreateWithFlags(&evJoin, cudaEventDisableTiming);
    }

    dim3 aggGrid((N_NODES + 7) / 8);            // warp per node
    int gemmGrid = (N_NODES + 255) / 256;       // 391

    // ---- fork: gemm0 (Y0 = feat @ W0 -> fp16, independent of CSR) on s2 ----
    cudaEventRecord(evFork, 0);
    cudaStreamWaitEvent(s2, evFork, 0);
    k_gemm_tc<128, false><<<gemmGrid, 512, SM_GEMM, s2>>>(features, W0, bufY);
    cudaEventRecord(evJoin, s2);

    // ---- CSR build (by dst), concurrent with gemm0 ----
    cudaMemsetAsync(countsPtr, 0, N_NODES * sizeof(int));
    k_hist<<<(N_EDGES + 255) / 256, 256>>>(dst);
    int nb = (N_NODES + 1023) / 1024;   // 98
    k_scan1<<<nb, 1024>>>();
    k_scan2<<<1, 128>>>(nb);
    k_scan3<<<(N_NODES + 1 + 255) / 256, 256>>>();
    k_scatter<<<(N_EDGES + 255) / 256, 256>>>(src, dst);

    cudaStreamWaitEvent(0, evJoin, 0);

    // layer 0 epilogue: h1 = relu(norm * segsum(Y0[src]) + b0)  (fp16 in/out)
    k_agg16_epi<<<aggGrid, 256>>>(bufY, norm, b0, bufH);
    // layer 1: Y1 = h1 @ W1 (fp16 A) ; h2 = relu(norm*segsum(Y1)+b1)
    k_gemm_tc<128, true><<<gemmGrid, 512, SM_GEMM>>>(bufH, W1, bufY);
    k_agg16_epi<<<aggGrid, 256>>>(bufY, norm, b1, bufH);
    // layer 2: Y2 = h2 @ W2 (fp16, 64-wide) ; out = norm*segsum(Y2)+b2 (fp32)
    k_gemm_tc<64, true><<<gemmGrid, 512, SM_GEMM>>>(bufH, W2, bufY);
    k_agg64_bias<<<aggGrid, 256>>>(bufY, norm, b2, out);
}